// round 13
// baseline (speedup 1.0000x reference)
#include <cuda_runtime.h>

typedef unsigned long long u64;

#define BATCH 64
#define TLEN  2048
#define TM1   2047
#define CIN   8
#define MD    16
#define NOUT  10

#define CHUNK  64
#define NCHUNK 32            // 32*64 = 2048 >= 2047 (tail -> identity)
#define NGRP   8             // 16-thread groups per block
#define SPG    8             // steps per group
#define STR    20            // padded row stride (floats)
#define SLOT   (MD*STR)      // 320 floats per matrix slot
#define GSTR   (3*SLOT + 4)  // per-group: sA + sB + sZ + pad

// chunk partial products: [B][NCHUNK][16][16]
__device__ float g_partial[BATCH * NCHUNK * MD * MD];

// ---- packed f32x2 helpers ----
__device__ __forceinline__ float2 unpk(u64 v) {
  float2 r; asm("mov.b64 {%0,%1}, %2;" : "=f"(r.x), "=f"(r.y) : "l"(v)); return r;
}
__device__ __forceinline__ u64 pk2(float x, float y) {
  u64 r; asm("mov.b64 %0, {%1,%2};" : "=l"(r) : "f"(x), "f"(y)); return r;
}
__device__ __forceinline__ u64 bc2(float x) {
  u64 r; asm("mov.b64 %0, {%1,%1};" : "=l"(r) : "f"(x)); return r;
}
__device__ __forceinline__ void fma2(u64& d, u64 a, u64 b) {
  asm("fma.rn.f32x2 %0, %1, %2, %0;" : "+l"(d) : "l"(a), "l"(b));
}
__device__ __forceinline__ u64 fma2v(u64 a, u64 b, u64 c) {
  u64 d; asm("fma.rn.f32x2 %0, %1, %2, %3;" : "=l"(d) : "l"(a), "l"(b), "l"(c)); return d;
}
__device__ __forceinline__ u64 mul2(u64 a, u64 b) {
  u64 d; asm("mul.rn.f32x2 %0, %1, %2;" : "=l"(d) : "l"(a), "l"(b)); return d;
}

// acc += av * Brow (16 floats in smem, 16B-aligned)
__device__ __forceinline__ void row_fma(u64* acc, u64 av, const float* brow) {
  const ulonglong2* bp = reinterpret_cast<const ulonglong2*>(brow);
  ulonglong2 b0 = bp[0], b1 = bp[1], b2 = bp[2], b3 = bp[3];
  fma2(acc[0], av, b0.x); fma2(acc[1], av, b0.y);
  fma2(acc[2], av, b1.x); fma2(acc[3], av, b1.y);
  fma2(acc[4], av, b2.x); fma2(acc[5], av, b2.y);
  fma2(acc[6], av, b3.x); fma2(acc[7], av, b3.y);
}

// STAGED matmul: identical LDS.128 stream to the champion (full unroll,
// static addresses), but a volatile-asm data dependency chains each stage's
// addresses to the previous stage's first FMA result. ptxas therefore CANNOT
// hoist all 16 row-loads (255-reg appetite) -> live window ~1.5 stages
// (~48 regs), enabling 3 CTAs/SM without touching the memory stream.
__device__ __forceinline__ void mm_row2(const float* __restrict__ Bm,
                                        const u64* __restrict__ a,
                                        u64* __restrict__ acc) {
  unsigned int dep = 0;
#pragma unroll
  for (int kp = 0; kp < 8; kp++) {
    const float* B0 = Bm + (2 * kp) * STR + dep;      // dep == 0 always
    const float* B1 = Bm + (2 * kp + 1) * STR + dep;
    float2 ak = unpk(a[kp]);
    row_fma(acc, bc2(ak.x), B0);
    row_fma(acc, bc2(ak.y), B1);
    if (kp < 7)
      asm volatile("mov.b32 %0, 0;" : "=r"(dep) : "l"(acc[0]));
  }
}

// plain full-unroll variant for the tiny finalize kernel (no reg pressure)
__device__ __forceinline__ void mm_row2f(const float* __restrict__ Bm,
                                         const u64* __restrict__ a,
                                         u64* __restrict__ acc) {
#pragma unroll
  for (int kp = 0; kp < 8; kp++) {
    float2 ak = unpk(a[kp]);
    row_fma(acc, bc2(ak.x), Bm + (2 * kp) * STR);
    row_fma(acc, bc2(ak.y), Bm + (2 * kp + 1) * STR);
  }
}

__device__ __forceinline__ void store_row2(float* dst, const u64* v) {
  ulonglong2* dp = reinterpret_cast<ulonglong2*>(dst);
  dp[0] = make_ulonglong2(v[0], v[1]);
  dp[1] = make_ulonglong2(v[2], v[3]);
  dp[2] = make_ulonglong2(v[4], v[5]);
  dp[3] = make_ulonglong2(v[6], v[7]);
}
__device__ __forceinline__ void load_row2(const float* src, u64* v) {
  const ulonglong2* sp = reinterpret_cast<const ulonglong2*>(src);
  ulonglong2 a = sp[0], b = sp[1], c = sp[2], d = sp[3];
  v[0] = a.x; v[1] = a.y; v[2] = b.x; v[3] = b.y;
  v[4] = c.x; v[5] = c.y; v[6] = d.x; v[7] = d.y;
}

// pad kernel (period-3 launch pattern c,f,n -> ncu "-s 5" lands on dev_chunks)
__global__ void nopk() {}

// ---------------------------------------------------------------------------
// Kernel 1: per (batch, chunk of 64 steps). R9 math exactly (commuting-
// Horner Taylor-6 at theta<=0.25, warp-uniform squarings, ping-pong).
// NEW: dependency-staged loads + launch_bounds(128,3) -> 12 warps/SM.
// ---------------------------------------------------------------------------
__global__ void __launch_bounds__(128, 3) dev_chunks(const float* __restrict__ X,
                                                     const float* __restrict__ A) {
  __shared__ __align__(16) float Gs[CIN * SLOT];
  __shared__ __align__(16) float slots[NGRP * GSTR];
  __shared__ float dxs[CHUNK * CIN];

  const int tid   = threadIdx.x;
  const int chunk = blockIdx.x;
  const int b     = blockIdx.y;
  const int base  = chunk * CHUNK;

  for (int idx = tid; idx < CIN * MD * MD; idx += 128) {
    int c = idx >> 8;
    int i = (idx >> 4) & 15;
    int j = idx & 15;
    Gs[c * SLOT + i * STR + j] =
        A[(i * MD + j) * CIN + c] - A[(j * MD + i) * CIN + c];
  }
  for (int idx = tid; idx < CHUNK * CIN; idx += 128) {
    int k = idx >> 3;
    int c = idx & 7;
    int t = base + k;
    float v = 0.f;
    if (t < TM1)
      v = X[(b * TLEN + t + 1) * CIN + c] - X[(b * TLEN + t) * CIN + c];
    dxs[idx] = v;
  }
  __syncthreads();

  const int grp = tid >> 4;
  const int li  = tid & 15;
  float* sA = slots + grp * GSTR;   // S + odd squarings
  float* sB = sA + SLOT;            // even squarings
  float* sZ = sB + SLOT;            // running product Z

  u64 idp[8];
#pragma unroll
  for (int p = 0; p < 8; p++)
    idp[p] = pk2((li == 2 * p) ? 1.f : 0.f, (li == 2 * p + 1) ? 1.f : 0.f);

  u64 cur[8];

  for (int kl = 0; kl < SPG; kl++) {
    const int kk = grp * SPG + kl;

    // ---- S row (packed), staged like the mm ----
    u64 S[8];
#pragma unroll
    for (int p = 0; p < 8; p++) S[p] = 0ull;
    {
      unsigned int dep = 0;
#pragma unroll
      for (int c = 0; c < CIN; c++) {
        u64 d2 = bc2(dxs[kk * CIN + c]);
        row_fma(S, d2, Gs + c * SLOT + li * STR + dep);
        if (c < CIN - 1)
          asm volatile("mov.b32 %0, 0;" : "=r"(dep) : "l"(S[0]));
      }
    }

    // ---- norm: min(inf, Frobenius/sqrt(2)); warp-uniform s ----
    float rs = 0.f, fr = 0.f;
#pragma unroll
    for (int p = 0; p < 8; p++) {
      float2 t = unpk(S[p]);
      rs += fabsf(t.x) + fabsf(t.y);
      fr = fmaf(t.x, t.x, fr);
      fr = fmaf(t.y, t.y, fr);
    }
#pragma unroll
    for (int off = 1; off < 16; off <<= 1) {
      rs = fmaxf(rs, __shfl_xor_sync(0xffffffffu, rs, off));
      fr += __shfl_xor_sync(0xffffffffu, fr, off);
    }
    float nrm = fminf(rs, sqrtf(0.5f * fr));
    nrm = fmaxf(nrm, __shfl_xor_sync(0xffffffffu, nrm, 16));  // warp-uniform
    int s = 0;
    if (nrm > 0.f) {
      int e;
      frexpf(nrm, &e);   // nrm = f * 2^e, f in [0.5,1)
      s = e + 2;         // ||S/2^s|| <= 0.25
      if (s < 0) s = 0;
      if (s > 40) s = 40;
    }
    const u64 sc2 = bc2(__int_as_float((127 - s) << 23));  // exact 2^-s
#pragma unroll
    for (int p = 0; p < 8; p++) S[p] = mul2(S[p], sc2);

    // ---- store S once; init Horner while the STS is in flight ----
    store_row2(sA + li * STR, S);
    {
      const u64 c6 = bc2(1.f / 6.f);
#pragma unroll
      for (int p = 0; p < 8; p++) cur[p] = fma2v(S[p], c6, idp[p]);
    }
    __syncwarp();

    // ---- commuting-Horner Taylor-6: no syncs, S read from sA ----
#pragma unroll
    for (int k = 5; k >= 1; k--) {
      u64 acc[8];
#pragma unroll
      for (int p = 0; p < 8; p++) acc[p] = 0ull;
      mm_row2(sA, cur, acc);                  // acc = cur @ S (== S @ cur)
      const u64 inv = bc2(1.f / (float)k);
#pragma unroll
      for (int p = 0; p < 8; p++) cur[p] = fma2v(acc[p], inv, idp[p]);
    }

    // ---- warp-uniform squarings: ping-pong buffers, 1 sync each ----
    for (int q = 0; q < s; q++) {
      float* buf = (q & 1) ? sA : sB;
      store_row2(buf + li * STR, cur);
      __syncwarp();                           // store visible + old readers done
      u64 acc[8];
#pragma unroll
      for (int p = 0; p < 8; p++) acc[p] = 0ull;
      mm_row2(buf, cur, acc);
#pragma unroll
      for (int p = 0; p < 8; p++) cur[p] = acc[p];
    }

    // ---- fold: Z = M @ Z ----
    if (kl > 0) {
      u64 acc[8];
#pragma unroll
      for (int p = 0; p < 8; p++) acc[p] = 0ull;
      mm_row2(sZ, cur, acc);
#pragma unroll
      for (int p = 0; p < 8; p++) cur[p] = acc[p];
    }
    __syncwarp();                             // sZ readers done before overwrite
    store_row2(sZ + li * STR, cur);
    __syncwarp();
  }

  // ---- block tree over 8 group products (later factor on the left) ----
  __syncthreads();
  for (int cnt = NGRP; cnt > 1; cnt >>= 1) {
    int pairs = cnt >> 1;
    u64 acc[8];
    bool act = (grp < pairs);
    if (act) {
      u64 lrow[8];
      load_row2(slots + (2 * grp + 1) * GSTR + 2 * SLOT + li * STR, lrow);
#pragma unroll
      for (int p = 0; p < 8; p++) acc[p] = 0ull;
      mm_row2(slots + (2 * grp) * GSTR + 2 * SLOT, lrow, acc);
    }
    __syncthreads();
    if (act) store_row2(slots + grp * GSTR + 2 * SLOT + li * STR, acc);
    __syncthreads();
  }

  const float* Zf = slots + 2 * SLOT;  // group 0's Z slot
  for (int idx = tid; idx < MD * MD; idx += 128) {
    int i = idx >> 4, j = idx & 15;
    g_partial[(b * NCHUNK + chunk) * (MD * MD) + idx] = Zf[i * STR + j];
  }
}

// ---------------------------------------------------------------------------
// Kernel 2: per batch — tree over 32 chunk products, then linear head.
// ---------------------------------------------------------------------------
__global__ void __launch_bounds__(256) dev_finalize(const float* __restrict__ W,
                                                    const float* __restrict__ bias,
                                                    float* __restrict__ out) {
  __shared__ __align__(16) float bufs[NCHUNK * SLOT];  // 40 KB
  const int tid = threadIdx.x;
  const int b   = blockIdx.x;

  for (int idx = tid; idx < NCHUNK * MD * MD; idx += 256) {
    int cm = idx >> 8;
    int r  = idx & 255;
    bufs[cm * SLOT + (r >> 4) * STR + (r & 15)] =
        g_partial[b * NCHUNK * (MD * MD) + idx];
  }
  __syncthreads();

  const int grp = tid >> 4;
  const int li  = tid & 15;
  for (int cnt = NCHUNK; cnt > 1; cnt >>= 1) {
    int pairs = cnt >> 1;
    u64 acc[8];
    if (grp < pairs) {
      u64 lrow[8];
      load_row2(bufs + (2 * grp + 1) * SLOT + li * STR, lrow);
#pragma unroll
      for (int p = 0; p < 8; p++) acc[p] = 0ull;
      mm_row2f(bufs + (2 * grp) * SLOT, lrow, acc);
    }
    __syncthreads();
    if (grp < pairs) store_row2(bufs + grp * SLOT + li * STR, acc);
    __syncthreads();
  }

  if (tid < NOUT * 16) {
    const int o = tid >> 4;
    float p = 0.f;
#pragma unroll
    for (int j = 0; j < 16; j++)
      p = fmaf(bufs[li * STR + j], W[o * 256 + li * 16 + j], p);
#pragma unroll
    for (int off = 8; off > 0; off >>= 1)
      p += __shfl_xor_sync(0xffffffffu, p, off);
    if (li == 0) out[b * NOUT + o] = p + bias[o];
  }
}

extern "C" void kernel_launch(void* const* d_in, const int* in_sizes, int n_in,
                              void* d_out, int out_size) {
  const float* X = nullptr; const float* A = nullptr;
  const float* W = nullptr; const float* bv = nullptr;
  for (int i = 0; i < n_in; i++) {
    const float* p = (const float*)d_in[i];
    switch (in_sizes[i]) {
      case BATCH * TLEN * CIN: X = p; break;   // 1048576
      case MD * MD * CIN:      A = p; break;   // 2048
      case NOUT * MD * MD:     W = p; break;   // 2560
      case NOUT:               bv = p; break;  // 10
      default: break;
    }
  }
  float* out = (float*)d_out;

  dim3 g1(NCHUNK, BATCH);
  dev_chunks<<<g1, 128>>>(X, A);      // period-3 pattern: c,f,n
  dev_finalize<<<BATCH, 256>>>(W, bv, out);
  nopk<<<1, 32>>>();                  // ncu -s 5 -> global idx 5 = dev_chunks
}

// round 14
// speedup vs baseline: 1.3560x; 1.3560x over previous
#include <cuda_runtime.h>

typedef unsigned long long u64;

#define BATCH 64
#define TLEN  2048
#define TM1   2047
#define CIN   8
#define MD    16
#define NOUT  10

#define CHUNK  64
#define NCHUNK 32            // 32*64 = 2048 >= 2047 (tail -> identity)
#define NGRP   8             // 8 warp-groups per 256-thread block
#define SPG    8             // steps per group
#define STR    20            // padded row stride (floats)
#define SLOT   (MD*STR)      // 320 floats per matrix slot
#define GSTR   (2*SLOT + 4)  // per-group: sM (scratch) + sZ + pad

// chunk partial products: [B][NCHUNK][16][16]
__device__ float g_partial[BATCH * NCHUNK * MD * MD];

// ---- packed f32x2 helpers ----
__device__ __forceinline__ float2 unpk(u64 v) {
  float2 r; asm("mov.b64 {%0,%1}, %2;" : "=f"(r.x), "=f"(r.y) : "l"(v)); return r;
}
__device__ __forceinline__ u64 pk2(float x, float y) {
  u64 r; asm("mov.b64 %0, {%1,%2};" : "=l"(r) : "f"(x), "f"(y)); return r;
}
__device__ __forceinline__ u64 bc2(float x) {
  u64 r; asm("mov.b64 %0, {%1,%1};" : "=l"(r) : "f"(x)); return r;
}
__device__ __forceinline__ void fma2(u64& d, u64 a, u64 b) {
  asm("fma.rn.f32x2 %0, %1, %2, %0;" : "+l"(d) : "l"(a), "l"(b));
}
__device__ __forceinline__ u64 fma2v(u64 a, u64 b, u64 c) {
  u64 d; asm("fma.rn.f32x2 %0, %1, %2, %3;" : "=l"(d) : "l"(a), "l"(b), "l"(c)); return d;
}
__device__ __forceinline__ u64 mul2(u64 a, u64 b) {
  u64 d; asm("mul.rn.f32x2 %0, %1, %2;" : "=l"(d) : "l"(a), "l"(b)); return d;
}

// ---------------------------------------------------------------------------
// Warp-per-matrix layout: lane = h*16 + i  (i = row 0..15, h = column half).
// Thread (i,h) owns cols [8h, 8h+8) of row i (4 u64).
// ---------------------------------------------------------------------------

// assemble full row (8 u64, cols 0..15) from own half + partner's (lane^16)
__device__ __forceinline__ void exch_full(u64* full, const u64* half, int h) {
  u64 oth[4];
#pragma unroll
  for (int p = 0; p < 4; p++)
    oth[p] = __shfl_xor_sync(0xffffffffu, half[p], 16);
#pragma unroll
  for (int p = 0; p < 4; p++) {
    full[p]     = h ? oth[p]  : half[p];
    full[4 + p] = h ? half[p] : oth[p];
  }
}

// acc(half-row) += curFull(row regs) @ M(smem 16x16, rows at STR, half h)
__device__ __forceinline__ void mm_half(const float* __restrict__ Bm, int h,
                                        const u64* __restrict__ curF,
                                        u64* __restrict__ acc) {
#pragma unroll
  for (int kp = 0; kp < 8; kp++) {
    float2 a = unpk(curF[kp]);
    const ulonglong2* e = reinterpret_cast<const ulonglong2*>(Bm + (2 * kp) * STR + 8 * h);
    const ulonglong2* o = reinterpret_cast<const ulonglong2*>(Bm + (2 * kp + 1) * STR + 8 * h);
    ulonglong2 E = e[0], E1 = e[1];
    ulonglong2 O = o[0], O1 = o[1];
    u64 ax = bc2(a.x), ay = bc2(a.y);
    fma2(acc[0], ax, E.x);  fma2(acc[1], ax, E.y);
    fma2(acc[2], ax, E1.x); fma2(acc[3], ax, E1.y);
    fma2(acc[0], ay, O.x);  fma2(acc[1], ay, O.y);
    fma2(acc[2], ay, O1.x); fma2(acc[3], ay, O1.y);
  }
}

// acc(half-row) += curFull @ S where S's column-block lives in REGISTERS
// (Sblk[k*4+p] = cols [8h,8h+8) of row k). Zero LDS in the Horner phase.
__device__ __forceinline__ void mm_reg(const u64* __restrict__ Sblk,
                                       const u64* __restrict__ curF,
                                       u64* __restrict__ acc) {
#pragma unroll
  for (int kp = 0; kp < 8; kp++) {
    float2 a = unpk(curF[kp]);
    u64 ax = bc2(a.x), ay = bc2(a.y);
#pragma unroll
    for (int p = 0; p < 4; p++) {
      fma2(acc[p], ax, Sblk[(2 * kp) * 4 + p]);
      fma2(acc[p], ay, Sblk[(2 * kp + 1) * 4 + p]);
    }
  }
}

__device__ __forceinline__ void st_half(float* dst, const u64* v) {
  ulonglong2* dp = reinterpret_cast<ulonglong2*>(dst);
  dp[0] = make_ulonglong2(v[0], v[1]);
  dp[1] = make_ulonglong2(v[2], v[3]);
}
__device__ __forceinline__ void ld_full(const float* src, u64* v) {
  const ulonglong2* sp = reinterpret_cast<const ulonglong2*>(src);
  ulonglong2 a = sp[0], b = sp[1], c = sp[2], d = sp[3];
  v[0] = a.x; v[1] = a.y; v[2] = b.x; v[3] = b.y;
  v[4] = c.x; v[5] = c.y; v[6] = d.x; v[7] = d.y;
}

// pad kernel (period-3 launch pattern c,f,n -> ncu "-s 5" lands on dev_chunks)
__global__ void nopk() {}

// ---------------------------------------------------------------------------
// Kernel 1: 256 threads = 8 warps; each warp develops 8 steps of one chunk
// segment (one matrix at a time, 32 threads/matrix). expm = commuting-Horner
// Taylor-6 at theta<=0.25 with the S column-block in REGISTERS (Horner does
// no shared loads), warp-uniform (per-matrix exact) squarings via smem.
// ---------------------------------------------------------------------------
__global__ void __launch_bounds__(256) dev_chunks(const float* __restrict__ X,
                                                  const float* __restrict__ A) {
  __shared__ __align__(16) float Gs[CIN * SLOT];
  __shared__ __align__(16) float slots[NGRP * GSTR];
  __shared__ float dxs[CHUNK * CIN];

  const int tid   = threadIdx.x;
  const int chunk = blockIdx.x;
  const int b     = blockIdx.y;
  const int base  = chunk * CHUNK;

  for (int idx = tid; idx < CIN * MD * MD; idx += 256) {
    int c = idx >> 8;
    int i = (idx >> 4) & 15;
    int j = idx & 15;
    Gs[c * SLOT + i * STR + j] =
        A[(i * MD + j) * CIN + c] - A[(j * MD + i) * CIN + c];
  }
  for (int idx = tid; idx < CHUNK * CIN; idx += 256) {
    int k = idx >> 3;
    int c = idx & 7;
    int t = base + k;
    float v = 0.f;
    if (t < TM1)
      v = X[(b * TLEN + t + 1) * CIN + c] - X[(b * TLEN + t) * CIN + c];
    dxs[idx] = v;
  }
  __syncthreads();

  const int grp  = tid >> 5;        // warp id = group
  const int lane = tid & 31;
  const int i    = lane & 15;       // row
  const int h    = lane >> 4;       // column half
  float* sM = slots + grp * GSTR;   // scratch matrix (S, squarings)
  float* sZ = sM + SLOT;            // running product Z

  // identity half-row: cols [8h, 8h+8) of row i
  u64 idh[4];
#pragma unroll
  for (int p = 0; p < 4; p++)
    idh[p] = pk2((i == 8 * h + 2 * p) ? 1.f : 0.f,
                 (i == 8 * h + 2 * p + 1) ? 1.f : 0.f);

  u64 curF[8];   // full current row (cols 0..15)

  for (int kl = 0; kl < SPG; kl++) {
    const int kk = grp * SPG + kl;

    // ---- build S half-row: Sh = sum_c dx_c * G_c[i][8h..8h+8) ----
    u64 Sh[4];
#pragma unroll
    for (int p = 0; p < 4; p++) Sh[p] = 0ull;
#pragma unroll
    for (int c = 0; c < CIN; c++) {
      u64 d2 = bc2(dxs[kk * CIN + c]);
      const ulonglong2* gp =
          reinterpret_cast<const ulonglong2*>(Gs + c * SLOT + i * STR + 8 * h);
      ulonglong2 g0 = gp[0], g1 = gp[1];
      fma2(Sh[0], d2, g0.x); fma2(Sh[1], d2, g0.y);
      fma2(Sh[2], d2, g1.x); fma2(Sh[3], d2, g1.y);
    }

    // ---- norms: inf (row-sum max) and Frobenius; warp-uniform s ----
    float rs = 0.f, fr = 0.f;
#pragma unroll
    for (int p = 0; p < 4; p++) {
      float2 t = unpk(Sh[p]);
      rs += fabsf(t.x) + fabsf(t.y);
      fr = fmaf(t.x, t.x, fr);
      fr = fmaf(t.y, t.y, fr);
    }
    rs += __shfl_xor_sync(0xffffffffu, rs, 16);       // full row sum
#pragma unroll
    for (int off = 1; off < 16; off <<= 1)
      rs = fmaxf(rs, __shfl_xor_sync(0xffffffffu, rs, off));  // max over rows
#pragma unroll
    for (int off = 1; off < 32; off <<= 1)
      fr += __shfl_xor_sync(0xffffffffu, fr, off);     // full Frobenius^2
    float nrm = fminf(rs, sqrtf(0.5f * fr));
    int s = 0;
    if (nrm > 0.f) {
      int e;
      frexpf(nrm, &e);   // nrm = f * 2^e, f in [0.5,1)
      s = e + 2;         // ||S/2^s|| <= 0.25
      if (s < 0) s = 0;
      if (s > 40) s = 40;
    }
    const u64 sc2 = bc2(__int_as_float((127 - s) << 23));  // exact 2^-s
#pragma unroll
    for (int p = 0; p < 4; p++) Sh[p] = mul2(Sh[p], sc2);

    // ---- stage S in smem once, then pull the column-block into registers
    __syncwarp();                       // prior step's sM readers done
    st_half(sM + i * STR + 8 * h, Sh);
    __syncwarp();
    u64 Sblk[64];                       // S[k][8h..8h+8) for all k, in regs
#pragma unroll
    for (int k = 0; k < 16; k++) {
      const ulonglong2* sp =
          reinterpret_cast<const ulonglong2*>(sM + k * STR + 8 * h);
      ulonglong2 u0 = sp[0], u1 = sp[1];
      Sblk[k * 4 + 0] = u0.x; Sblk[k * 4 + 1] = u0.y;
      Sblk[k * 4 + 2] = u1.x; Sblk[k * 4 + 3] = u1.y;
    }

    // ---- init Horner: cur = I + S/6 (half), assemble full row ----
    {
      const u64 c6 = bc2(1.f / 6.f);
      u64 half[4];
#pragma unroll
      for (int p = 0; p < 4; p++) half[p] = fma2v(Sh[p], c6, idh[p]);
      exch_full(curF, half, h);
    }

    // ---- commuting-Horner Taylor-6: register S-block, ZERO shared loads ----
#pragma unroll
    for (int k = 5; k >= 1; k--) {
      u64 acc[4];
#pragma unroll
      for (int p = 0; p < 4; p++) acc[p] = 0ull;
      mm_reg(Sblk, curF, acc);                 // acc = (cur @ S) half
      const u64 inv = bc2(1.f / (float)k);
      u64 half[4];
#pragma unroll
      for (int p = 0; p < 4; p++) half[p] = fma2v(acc[p], inv, idh[p]);
      exch_full(curF, half, h);
    }

    // ---- squarings (s exact for THIS matrix; warp-uniform) via smem ----
    for (int q = 0; q < s; q++) {
      __syncwarp();                            // prior sM readers done
      st_half(sM + i * STR + 8 * h, curF + 4 * h);   // own half
      __syncwarp();
      u64 acc[4];
#pragma unroll
      for (int p = 0; p < 4; p++) acc[p] = 0ull;
      mm_half(sM, h, curF, acc);
      u64 half[4];
#pragma unroll
      for (int p = 0; p < 4; p++) half[p] = acc[p];
      exch_full(curF, half, h);
    }

    // ---- fold: Z = M @ Z ----
    if (kl > 0) {
      u64 acc[4];
#pragma unroll
      for (int p = 0; p < 4; p++) acc[p] = 0ull;
      mm_half(sZ, h, curF, acc);
      u64 half[4];
#pragma unroll
      for (int p = 0; p < 4; p++) half[p] = acc[p];
      exch_full(curF, half, h);
    }
    __syncwarp();                              // sZ readers done
    st_half(sZ + i * STR + 8 * h, curF + 4 * h);
    __syncwarp();
  }

  // ---- block tree over 8 group products (later factor on the left) ----
  __syncthreads();
  for (int cnt = NGRP; cnt > 1; cnt >>= 1) {
    int pairs = cnt >> 1;
    u64 acc[4];
    bool act = (grp < pairs);
    if (act) {
      u64 lrow[8];
      ld_full(slots + (2 * grp + 1) * GSTR + SLOT + i * STR, lrow);  // full row
#pragma unroll
      for (int p = 0; p < 4; p++) acc[p] = 0ull;
      mm_half(slots + (2 * grp) * GSTR + SLOT, h, lrow, acc);
    }
    __syncthreads();
    if (act) st_half(slots + grp * GSTR + SLOT + i * STR + 8 * h, acc);
    __syncthreads();
  }

  const float* Zf = slots + SLOT;  // group 0's Z slot
  for (int idx = tid; idx < MD * MD; idx += 256) {
    int r = idx >> 4, j = idx & 15;
    g_partial[(b * NCHUNK + chunk) * (MD * MD) + idx] = Zf[r * STR + j];
  }
}

// ---------------------------------------------------------------------------
// Kernel 2: per batch — tree over 32 chunk products, then linear head.
// (unchanged champion structure: 16-thread groups, full rows)
// ---------------------------------------------------------------------------
__device__ __forceinline__ void row_fma16(u64* acc, u64 av, const float* brow) {
  const ulonglong2* bp = reinterpret_cast<const ulonglong2*>(brow);
  ulonglong2 b0 = bp[0], b1 = bp[1], b2 = bp[2], b3 = bp[3];
  fma2(acc[0], av, b0.x); fma2(acc[1], av, b0.y);
  fma2(acc[2], av, b1.x); fma2(acc[3], av, b1.y);
  fma2(acc[4], av, b2.x); fma2(acc[5], av, b2.y);
  fma2(acc[6], av, b3.x); fma2(acc[7], av, b3.y);
}
__device__ __forceinline__ void mm_row2f(const float* __restrict__ Bm,
                                         const u64* __restrict__ a,
                                         u64* __restrict__ acc) {
#pragma unroll
  for (int kp = 0; kp < 8; kp++) {
    float2 ak = unpk(a[kp]);
    row_fma16(acc, bc2(ak.x), Bm + (2 * kp) * STR);
    row_fma16(acc, bc2(ak.y), Bm + (2 * kp + 1) * STR);
  }
}
__device__ __forceinline__ void store_row8(float* dst, const u64* v) {
  ulonglong2* dp = reinterpret_cast<ulonglong2*>(dst);
  dp[0] = make_ulonglong2(v[0], v[1]);
  dp[1] = make_ulonglong2(v[2], v[3]);
  dp[2] = make_ulonglong2(v[4], v[5]);
  dp[3] = make_ulonglong2(v[6], v[7]);
}

__global__ void __launch_bounds__(256) dev_finalize(const float* __restrict__ W,
                                                    const float* __restrict__ bias,
                                                    float* __restrict__ out) {
  __shared__ __align__(16) float bufs[NCHUNK * SLOT];  // 40 KB
  const int tid = threadIdx.x;
  const int b   = blockIdx.x;

  for (int idx = tid; idx < NCHUNK * MD * MD; idx += 256) {
    int cm = idx >> 8;
    int r  = idx & 255;
    bufs[cm * SLOT + (r >> 4) * STR + (r & 15)] =
        g_partial[b * NCHUNK * (MD * MD) + idx];
  }
  __syncthreads();

  const int grp = tid >> 4;
  const int li  = tid & 15;
  for (int cnt = NCHUNK; cnt > 1; cnt >>= 1) {
    int pairs = cnt >> 1;
    u64 acc[8];
    if (grp < pairs) {
      u64 lrow[8];
      ld_full(bufs + (2 * grp + 1) * SLOT + li * STR, lrow);
#pragma unroll
      for (int p = 0; p < 8; p++) acc[p] = 0ull;
      mm_row2f(bufs + (2 * grp) * SLOT, lrow, acc);
    }
    __syncthreads();
    if (grp < pairs) store_row8(bufs + grp * SLOT + li * STR, acc);
    __syncthreads();
  }

  if (tid < NOUT * 16) {
    const int o = tid >> 4;
    float p = 0.f;
#pragma unroll
    for (int j = 0; j < 16; j++)
      p = fmaf(bufs[li * STR + j], W[o * 256 + li * 16 + j], p);
#pragma unroll
    for (int off = 8; off > 0; off >>= 1)
      p += __shfl_xor_sync(0xffffffffu, p, off);
    if (li == 0) out[b * NOUT + o] = p + bias[o];
  }
}

extern "C" void kernel_launch(void* const* d_in, const int* in_sizes, int n_in,
                              void* d_out, int out_size) {
  const float* X = nullptr; const float* A = nullptr;
  const float* W = nullptr; const float* bv = nullptr;
  for (int i = 0; i < n_in; i++) {
    const float* p = (const float*)d_in[i];
    switch (in_sizes[i]) {
      case BATCH * TLEN * CIN: X = p; break;   // 1048576
      case MD * MD * CIN:      A = p; break;   // 2048
      case NOUT * MD * MD:     W = p; break;   // 2560
      case NOUT:               bv = p; break;  // 10
      default: break;
    }
  }
  float* out = (float*)d_out;

  dim3 g1(NCHUNK, BATCH);
  dev_chunks<<<g1, 256>>>(X, A);      // period-3 pattern: c,f,n
  dev_finalize<<<BATCH, 256>>>(W, bv, out);
  nopk<<<1, 32>>>();                  // ncu -s 5 -> global idx 5 = dev_chunks
}

// round 15
// speedup vs baseline: 1.6359x; 1.2064x over previous
#include <cuda_runtime.h>

typedef unsigned long long u64;

#define BATCH 64
#define TLEN  2048
#define TM1   2047
#define CIN   8
#define MD    16
#define NOUT  10

#define CHUNK  64
#define NCHUNK 32            // 32*64 = 2048 >= 2047 (tail -> identity)
#define NGRP   8             // 16-thread groups per block
#define SPG    8             // steps per group
#define STR    20            // padded row stride (floats)
#define SLOT   (MD*STR)      // 320 floats per matrix slot
#define GSTR   (2*SLOT + 4)  // per-group region: S/scratch slot + Z slot + pad

// chunk partial products: [B][NCHUNK][16][16]
__device__ float g_partial[BATCH * NCHUNK * MD * MD];

// ---- packed f32x2 helpers (Blackwell FFMA2 path) ----
__device__ __forceinline__ float2 unpk(u64 v) {
  float2 r; asm("mov.b64 {%0,%1}, %2;" : "=f"(r.x), "=f"(r.y) : "l"(v)); return r;
}
__device__ __forceinline__ u64 pk2(float x, float y) {
  u64 r; asm("mov.b64 %0, {%1,%2};" : "=l"(r) : "f"(x), "f"(y)); return r;
}
__device__ __forceinline__ u64 bc2(float x) {
  u64 r; asm("mov.b64 %0, {%1,%1};" : "=l"(r) : "f"(x)); return r;
}
__device__ __forceinline__ void fma2(u64& d, u64 a, u64 b) {
  asm("fma.rn.f32x2 %0, %1, %2, %0;" : "+l"(d) : "l"(a), "l"(b));
}
__device__ __forceinline__ u64 fma2v(u64 a, u64 b, u64 c) {
  u64 d; asm("fma.rn.f32x2 %0, %1, %2, %3;" : "=l"(d) : "l"(a), "l"(b), "l"(c)); return d;
}
__device__ __forceinline__ u64 mul2(u64 a, u64 b) {
  u64 d; asm("mul.rn.f32x2 %0, %1, %2;" : "=l"(d) : "l"(a), "l"(b)); return d;
}

// acc += av * Brow (16 floats in smem, 16B-aligned)
__device__ __forceinline__ void row_fma(u64* acc, u64 av, const float* brow) {
  const ulonglong2* bp = reinterpret_cast<const ulonglong2*>(brow);
  ulonglong2 b0 = bp[0], b1 = bp[1], b2 = bp[2], b3 = bp[3];
  fma2(acc[0], av, b0.x); fma2(acc[1], av, b0.y);
  fma2(acc[2], av, b1.x); fma2(acc[3], av, b1.y);
  fma2(acc[4], av, b2.x); fma2(acc[5], av, b2.y);
  fma2(acc[6], av, b3.x); fma2(acc[7], av, b3.y);
}

// acc(row) += a(row, packed regs) @ Bm (16x16 in smem, row stride STR)
__device__ __forceinline__ void mm_row2(const float* __restrict__ Bm,
                                        const u64* __restrict__ a,
                                        u64* __restrict__ acc) {
#pragma unroll
  for (int kp = 0; kp < 8; kp++) {
    float2 ak = unpk(a[kp]);
    row_fma(acc, bc2(ak.x), Bm + (2 * kp) * STR);
    row_fma(acc, bc2(ak.y), Bm + (2 * kp + 1) * STR);
  }
}

__device__ __forceinline__ void store_row2(float* dst, const u64* v) {
  ulonglong2* dp = reinterpret_cast<ulonglong2*>(dst);
  dp[0] = make_ulonglong2(v[0], v[1]);
  dp[1] = make_ulonglong2(v[2], v[3]);
  dp[2] = make_ulonglong2(v[4], v[5]);
  dp[3] = make_ulonglong2(v[6], v[7]);
}
__device__ __forceinline__ void load_row2(const float* src, u64* v) {
  const ulonglong2* sp = reinterpret_cast<const ulonglong2*>(src);
  ulonglong2 a = sp[0], b = sp[1], c = sp[2], d = sp[3];
  v[0] = a.x; v[1] = a.y; v[2] = b.x; v[3] = b.y;
  v[4] = c.x; v[5] = c.y; v[6] = d.x; v[7] = d.y;
}

// ---------------------------------------------------------------------------
// Kernel 1: per (batch, chunk of 64 steps): build S, expm via commuting-
// Horner Taylor-6 (theta<=0.25) + warp-uniform squarings, fold, block tree.
// 16-thread groups, 1 row/thread. Champion configuration (measured 440.8us):
// full-unroll mm, no launch_bounds cap (ptxas 255 regs, 2 CTAs/SM).
// ---------------------------------------------------------------------------
__global__ void __launch_bounds__(128) dev_chunks(const float* __restrict__ X,
                                                  const float* __restrict__ A) {
  __shared__ __align__(16) float Gs[CIN * SLOT];          // A - A^T per channel
  __shared__ __align__(16) float slots[NGRP * GSTR];      // 2 slots/group
  __shared__ float dxs[CHUNK * CIN];

  const int tid   = threadIdx.x;
  const int chunk = blockIdx.x;
  const int b     = blockIdx.y;
  const int base  = chunk * CHUNK;

  for (int idx = tid; idx < CIN * MD * MD; idx += 128) {
    int c = idx >> 8;
    int i = (idx >> 4) & 15;
    int j = idx & 15;
    Gs[c * SLOT + i * STR + j] =
        A[(i * MD + j) * CIN + c] - A[(j * MD + i) * CIN + c];
  }
  for (int idx = tid; idx < CHUNK * CIN; idx += 128) {
    int k = idx >> 3;
    int c = idx & 7;
    int t = base + k;
    float v = 0.f;
    if (t < TM1)
      v = X[(b * TLEN + t + 1) * CIN + c] - X[(b * TLEN + t) * CIN + c];
    dxs[idx] = v;
  }
  __syncthreads();

  const int grp = tid >> 4;
  const int li  = tid & 15;
  float* gS = slots + grp * GSTR;   // S / squaring scratch
  float* gZ = gS + SLOT;            // running product Z

  // identity row (packed), per thread
  u64 idp[8];
#pragma unroll
  for (int p = 0; p < 8; p++)
    idp[p] = pk2((li == 2 * p) ? 1.f : 0.f, (li == 2 * p + 1) ? 1.f : 0.f);

  u64 cur[8];

  for (int kl = 0; kl < SPG; kl++) {
    const int kk = grp * SPG + kl;

    // ---- S row (packed) ----
    u64 S[8];
#pragma unroll
    for (int p = 0; p < 8; p++) S[p] = 0ull;
#pragma unroll
    for (int c = 0; c < CIN; c++) {
      u64 d2 = bc2(dxs[kk * CIN + c]);
      row_fma(S, d2, Gs + c * SLOT + li * STR);
    }

    // ---- norm: min(inf-norm, Frobenius/sqrt(2)); warp-uniform s ----
    float rs = 0.f, fr = 0.f;
#pragma unroll
    for (int p = 0; p < 8; p++) {
      float2 t = unpk(S[p]);
      rs += fabsf(t.x) + fabsf(t.y);
      fr = fmaf(t.x, t.x, fr);
      fr = fmaf(t.y, t.y, fr);
    }
#pragma unroll
    for (int off = 1; off < 16; off <<= 1) {         // within 16-lane group
      rs = fmaxf(rs, __shfl_xor_sync(0xffffffffu, rs, off));
      fr += __shfl_xor_sync(0xffffffffu, fr, off);
    }
    float nrm = fminf(rs, sqrtf(0.5f * fr));
    nrm = fmaxf(nrm, __shfl_xor_sync(0xffffffffu, nrm, 16));  // warp-uniform
    int s = 0;
    if (nrm > 0.f) {
      int e;
      frexpf(nrm, &e);   // nrm = f * 2^e, f in [0.5,1)
      s = e + 2;         // ||S/2^s|| <= 0.25
      if (s < 0) s = 0;
      if (s > 40) s = 40;
    }
    const u64 sc2 = bc2(__int_as_float((127 - s) << 23));  // exact 2^-s
#pragma unroll
    for (int p = 0; p < 8; p++) S[p] = mul2(S[p], sc2);

    // store S once (prior readers of gS are this group's own threads; warp
    // flow is uniform, so full-warp syncs are legal and cheap)
    __syncwarp();
    store_row2(gS + li * STR, S);
    __syncwarp();

    // ---- Taylor-6 Horner via commutativity: cur stays in registers ----
    // P = I + S(I + S/2(I + S/3(I + S/4(I + S/5(I + S/6)))));  cur@S == S@cur
    {
      const u64 c6 = bc2(1.f / 6.f);
#pragma unroll
      for (int p = 0; p < 8; p++) cur[p] = fma2v(S[p], c6, idp[p]);
    }
#pragma unroll
    for (int k = 5; k >= 1; k--) {
      u64 acc[8];
#pragma unroll
      for (int p = 0; p < 8; p++) acc[p] = 0ull;
      mm_row2(gS, cur, acc);                  // acc = cur @ S  (== S @ cur)
      const u64 inv = bc2(1.f / (float)k);
#pragma unroll
      for (int p = 0; p < 8; p++) cur[p] = fma2v(acc[p], inv, idp[p]);
    }

    // ---- warp-uniform squarings (scratch = gS, S no longer needed) ----
    for (int q = 0; q < s; q++) {
      __syncwarp();
      store_row2(gS + li * STR, cur);
      __syncwarp();
      u64 acc[8];
#pragma unroll
      for (int p = 0; p < 8; p++) acc[p] = 0ull;
      mm_row2(gS, cur, acc);
#pragma unroll
      for (int p = 0; p < 8; p++) cur[p] = acc[p];
    }

    // ---- fold: Z = M @ Z ----
    if (kl > 0) {
      u64 acc[8];
#pragma unroll
      for (int p = 0; p < 8; p++) acc[p] = 0ull;
      mm_row2(gZ, cur, acc);                  // rows of M (regs) @ Z (smem)
#pragma unroll
      for (int p = 0; p < 8; p++) cur[p] = acc[p];
    }
    __syncwarp();
    store_row2(gZ + li * STR, cur);
    __syncwarp();
  }

  // ---- block tree over 8 group products (later factor on the left) ----
  __syncthreads();
  for (int cnt = NGRP; cnt > 1; cnt >>= 1) {
    int pairs = cnt >> 1;
    u64 acc[8];
    bool act = (grp < pairs);
    if (act) {
      u64 lrow[8];
      load_row2(slots + (2 * grp + 1) * GSTR + SLOT + li * STR, lrow);
#pragma unroll
      for (int p = 0; p < 8; p++) acc[p] = 0ull;
      mm_row2(slots + (2 * grp) * GSTR + SLOT, lrow, acc);
    }
    __syncthreads();
    if (act) store_row2(slots + grp * GSTR + SLOT + li * STR, acc);
    __syncthreads();
  }

  const float* Zf = slots + SLOT;  // group 0's Z slot
  for (int idx = tid; idx < MD * MD; idx += 128) {
    int i = idx >> 4, j = idx & 15;
    g_partial[(b * NCHUNK + chunk) * (MD * MD) + idx] = Zf[i * STR + j];
  }
}

// ---------------------------------------------------------------------------
// Kernel 2: per batch — tree over 32 chunk products, then linear head.
// ---------------------------------------------------------------------------
__global__ void __launch_bounds__(256) dev_finalize(const float* __restrict__ W,
                                                    const float* __restrict__ bias,
                                                    float* __restrict__ out) {
  __shared__ __align__(16) float bufs[NCHUNK * SLOT];  // 40 KB
  const int tid = threadIdx.x;
  const int b   = blockIdx.x;

  for (int idx = tid; idx < NCHUNK * MD * MD; idx += 256) {
    int cm = idx >> 8;
    int r  = idx & 255;
    bufs[cm * SLOT + (r >> 4) * STR + (r & 15)] =
        g_partial[b * NCHUNK * (MD * MD) + idx];
  }
  __syncthreads();

  const int grp = tid >> 4;
  const int li  = tid & 15;
  for (int cnt = NCHUNK; cnt > 1; cnt >>= 1) {
    int pairs = cnt >> 1;
    u64 acc[8];
    if (grp < pairs) {
      u64 lrow[8];
      load_row2(bufs + (2 * grp + 1) * SLOT + li * STR, lrow);
#pragma unroll
      for (int p = 0; p < 8; p++) acc[p] = 0ull;
      mm_row2(bufs + (2 * grp) * SLOT, lrow, acc);
    }
    __syncthreads();
    if (grp < pairs) store_row2(bufs + grp * SLOT + li * STR, acc);
    __syncthreads();
  }

  if (tid < NOUT * 16) {
    const int o = tid >> 4;
    float p = 0.f;
#pragma unroll
    for (int j = 0; j < 16; j++)
      p = fmaf(bufs[li * STR + j], W[o * 256 + li * 16 + j], p);
#pragma unroll
    for (int off = 8; off > 0; off >>= 1)
      p += __shfl_xor_sync(0xffffffffu, p, off);
    if (li == 0) out[b * NOUT + o] = p + bias[o];
  }
}

extern "C" void kernel_launch(void* const* d_in, const int* in_sizes, int n_in,
                              void* d_out, int out_size) {
  const float* X = nullptr; const float* A = nullptr;
  const float* W = nullptr; const float* bv = nullptr;
  for (int i = 0; i < n_in; i++) {
    const float* p = (const float*)d_in[i];
    switch (in_sizes[i]) {
      case BATCH * TLEN * CIN: X = p; break;   // 1048576
      case MD * MD * CIN:      A = p; break;   // 2048
      case NOUT * MD * MD:     W = p; break;   // 2560
      case NOUT:               bv = p; break;  // 10
      default: break;
    }
  }
  float* out = (float*)d_out;

  dim3 g1(NCHUNK, BATCH);
  dev_chunks<<<g1, 128>>>(X, A);
  dev_finalize<<<BATCH, 256>>>(W, bv, out);
}